// round 11
// baseline (speedup 1.0000x reference)
#include <cuda_runtime.h>
#include <cuda_fp16.h>
#include <cstdint>

// MoE grouped GEMM, sm_103 base ISA: plain fp16 mma.sync.m16n8k16, fp32 accum.
// CTA tile 128x256, BK=32, 8 warps (2x4 grid of 64x64 warp tiles -> 128 B/MMA
// fragment traffic), 2-stage fp16 smem pipeline, B via cp.async fp32 staging,
// A register-prefetch.

#define BM 128
#define BN 256
#define BK 32
#define NTH 256

#define ASTR 40      // halves per A row (80 B) -> conflict-free ldmatrix
#define BSTR 264     // halves per B row (528 B) -> conflict-free ldmatrix.trans

// dynamic smem layout (bytes)
#define AH_OFF(s)  ((s) * 10240)              // 128*80 per stage
#define BH_OFF(s)  (20480 + (s) * 16896)      // 32*528 per stage
#define B32_OFF    54272                      // fp32 staging: 32 rows * 1024 B
#define SMEM_TOTAL 87040

static __device__ __forceinline__ uint32_t smem_u32(const void* p) {
    uint32_t a;
    asm("{ .reg .u64 t; cvta.to.shared.u64 t, %1; cvt.u32.u64 %0, t; }" : "=r"(a) : "l"(p));
    return a;
}
static __device__ __forceinline__ void cp_async16(uint32_t s, const void* g) {
    asm volatile("cp.async.cg.shared.global [%0], [%1], 16;" :: "r"(s), "l"(g));
}
#define CP_COMMIT() asm volatile("cp.async.commit_group;" ::: "memory")
#define CP_WAIT0()  asm volatile("cp.async.wait_group 0;" ::: "memory")

static __device__ __forceinline__ void ldsm4(uint32_t& r0, uint32_t& r1, uint32_t& r2, uint32_t& r3, uint32_t a) {
    asm volatile("ldmatrix.sync.aligned.m8n8.x4.shared.b16 {%0,%1,%2,%3}, [%4];"
                 : "=r"(r0), "=r"(r1), "=r"(r2), "=r"(r3) : "r"(a));
}
static __device__ __forceinline__ void ldsm4t(uint32_t& r0, uint32_t& r1, uint32_t& r2, uint32_t& r3, uint32_t a) {
    asm volatile("ldmatrix.sync.aligned.m8n8.x4.trans.shared.b16 {%0,%1,%2,%3}, [%4];"
                 : "=r"(r0), "=r"(r1), "=r"(r2), "=r"(r3) : "r"(a));
}
static __device__ __forceinline__ void mma16816(float* c, const uint32_t* a, uint32_t b0, uint32_t b1) {
    asm volatile("mma.sync.aligned.m16n8k16.row.col.f32.f16.f16.f32 "
                 "{%0,%1,%2,%3}, {%4,%5,%6,%7}, {%8,%9}, {%0,%1,%2,%3};"
                 : "+f"(c[0]), "+f"(c[1]), "+f"(c[2]), "+f"(c[3])
                 : "r"(a[0]), "r"(a[1]), "r"(a[2]), "r"(a[3]), "r"(b0), "r"(b1));
}
static __device__ __forceinline__ uint32_t h2u(__half2 h) { return *reinterpret_cast<uint32_t*>(&h); }
static __device__ __forceinline__ uint2 cvt4h(float x0, float x1, float x2, float x3) {
    return make_uint2(h2u(__floats2half2_rn(x0, x1)), h2u(__floats2half2_rn(x2, x3)));
}

__global__ __launch_bounds__(NTH, 1)
void moe_mma6(const float* __restrict__ A,
              const int*   __restrict__ gs,
              const float* __restrict__ W,
              const float* __restrict__ bias,
              float*       __restrict__ out,
              int T, int I, int O, int E)
{
    extern __shared__ char smem[];
    const int tid  = threadIdx.x;
    const int wid  = tid >> 5;
    const int lane = tid & 31;
    const int row0 = blockIdx.y * BM;
    const int col0 = blockIdx.x * BN;

    int e = 0, pref = 0;
    while (e < E - 1) {
        int g = __ldg(&gs[e]);
        if (row0 < pref + g) break;
        pref += g; e++;
    }
    const float* __restrict__ Wp = W + (size_t)e * I * O;

    const uint32_t sb = smem_u32(smem);
    // 8 warps: 2 rows (wm, 64 each) x 4 cols (wn, 64 each)
    const int wm = wid & 1, wn = wid >> 1;

    float acc[4][8][4];
    #pragma unroll
    for (int mi = 0; mi < 4; ++mi)
        #pragma unroll
        for (int ni = 0; ni < 8; ++ni)
            #pragma unroll
            for (int q = 0; q < 4; ++q) acc[mi][ni][q] = 0.f;

    const int nk = I / BK;

    // A load mapping: 128 rows x 8 float4-cols = 1024 float4, 256 thr -> 4 each
    const int ar = tid >> 3, ac4 = tid & 7;   // rows ar + 32*it
    // B cp.async / convert mapping: 32 rows x 64 16B-chunks = 2048, -> 8 each
    const int brow = tid >> 3, bchunk = tid & 7;   // chunks bchunk + 8*it

    float4 pa[4];

    // ---- prologue: tile 0 ----
    #pragma unroll
    for (int it = 0; it < 4; ++it)
        pa[it] = *(const float4*)(A + (size_t)(row0 + ar + it * 32) * I + ac4 * 4);
    #pragma unroll
    for (int it = 0; it < 8; ++it) {
        int c = bchunk + it * 8;
        cp_async16(sb + B32_OFF + brow * 1024 + c * 16,
                   Wp + (size_t)brow * O + col0 + c * 4);
    }
    CP_COMMIT();
    #pragma unroll
    for (int it = 0; it < 4; ++it) {
        int r = ar + it * 32;
        *(uint2*)(smem + AH_OFF(0) + r * (ASTR * 2) + ac4 * 8) =
            cvt4h(pa[it].x, pa[it].y, pa[it].z, pa[it].w);
    }
    CP_WAIT0();
    __syncthreads();
    #pragma unroll
    for (int it = 0; it < 8; ++it) {
        int c = bchunk + it * 8;
        float4 v = *(const float4*)(smem + B32_OFF + brow * 1024 + c * 16);
        *(uint2*)(smem + BH_OFF(0) + brow * (BSTR * 2) + c * 8) =
            cvt4h(v.x, v.y, v.z, v.w);
    }
    __syncthreads();

    for (int kt = 0; kt < nk; ++kt) {
        const int s = kt & 1;
        const bool more = (kt + 1 < nk);

        // issue gmem loads for tile kt+1
        if (more) {
            const int k0 = (kt + 1) * BK;
            #pragma unroll
            for (int it = 0; it < 4; ++it)
                pa[it] = *(const float4*)(A + (size_t)(row0 + ar + it * 32) * I + k0 + ac4 * 4);
            #pragma unroll
            for (int it = 0; it < 8; ++it) {
                int c = bchunk + it * 8;
                cp_async16(sb + B32_OFF + brow * 1024 + c * 16,
                           Wp + (size_t)(k0 + brow) * O + col0 + c * 4);
            }
            CP_COMMIT();
        }

        // ---- compute stage s: warp tile 64x64, 2 ks of k=16 ----
        const uint32_t sAh = sb + AH_OFF(s), sBh = sb + BH_OFF(s);
        #pragma unroll
        for (int ks = 0; ks < 2; ++ks) {
            uint32_t ah[4][4], bf[4][4];
            #pragma unroll
            for (int mi = 0; mi < 4; ++mi) {
                int row = wm * 64 + mi * 16 + (lane & 15);
                uint32_t off = row * (ASTR * 2) + ks * 32 + (lane >> 4) * 16;
                ldsm4(ah[mi][0], ah[mi][1], ah[mi][2], ah[mi][3], sAh + off);
            }
            #pragma unroll
            for (int nt = 0; nt < 4; ++nt) {
                int krow = ks * 16 + (lane & 15);
                int ncol = wn * 64 + nt * 16 + (lane >> 4) * 8;
                ldsm4t(bf[nt][0], bf[nt][1], bf[nt][2], bf[nt][3],
                       sBh + krow * (BSTR * 2) + ncol * 2);
            }
            #pragma unroll
            for (int mi = 0; mi < 4; ++mi)
                #pragma unroll
                for (int ni = 0; ni < 8; ++ni) {
                    uint32_t b0 = bf[ni >> 1][(ni & 1) * 2];
                    uint32_t b1 = bf[ni >> 1][(ni & 1) * 2 + 1];
                    mma16816(acc[mi][ni], ah[mi], b0, b1);
                }
        }

        // ---- convert tile kt+1 into stage s^1 ----
        if (more) {
            const int d = s ^ 1;
            #pragma unroll
            for (int it = 0; it < 4; ++it) {
                int r = ar + it * 32;
                *(uint2*)(smem + AH_OFF(d) + r * (ASTR * 2) + ac4 * 8) =
                    cvt4h(pa[it].x, pa[it].y, pa[it].z, pa[it].w);
            }
            CP_WAIT0();
            #pragma unroll
            for (int it = 0; it < 8; ++it) {
                int c = bchunk + it * 8;
                float4 v = *(const float4*)(smem + B32_OFF + brow * 1024 + c * 16);
                *(uint2*)(smem + BH_OFF(d) + brow * (BSTR * 2) + c * 8) =
                    cvt4h(v.x, v.y, v.z, v.w);
            }
        }
        __syncthreads();
    }

    // ---- epilogue: bias + store ----
    #pragma unroll
    for (int mi = 0; mi < 4; ++mi) {
        int r_lo = row0 + wm * 64 + mi * 16 + (lane >> 2);
        #pragma unroll
        for (int ni = 0; ni < 8; ++ni) {
            int col = col0 + wn * 64 + ni * 8 + (lane & 3) * 2;
            float2 bv = *(const float2*)(bias + (size_t)e * O + col);
            float2 v0, v1;
            v0.x = acc[mi][ni][0] + bv.x; v0.y = acc[mi][ni][1] + bv.y;
            v1.x = acc[mi][ni][2] + bv.x; v1.y = acc[mi][ni][3] + bv.y;
            *(float2*)(out + (size_t)r_lo * O + col) = v0;
            *(float2*)(out + (size_t)(r_lo + 8) * O + col) = v1;
        }
    }
}

extern "C" void kernel_launch(void* const* d_in, const int* in_sizes, int n_in,
                              void* d_out, int out_size)
{
    const float* A    = (const float*)d_in[0];
    const int*   gs   = (const int*)  d_in[1];
    const float* W    = (const float*)d_in[2];
    const float* bias = (const float*)d_in[3];
    float*       out  = (float*)d_out;

    const int E = in_sizes[1];
    const int O = in_sizes[3] / E;
    const long long wsz = (long long)in_sizes[2];
    const int I = (int)(wsz / ((long long)E * O));
    const int T = in_sizes[0] / I;

    cudaFuncSetAttribute(moe_mma6, cudaFuncAttributeMaxDynamicSharedMemorySize, SMEM_TOTAL);
    dim3 grid(O / BN, T / BM);
    moe_mma6<<<grid, NTH, SMEM_TOTAL>>>(A, gs, W, bias, out, T, I, O, E);
}

// round 12
// speedup vs baseline: 1.0932x; 1.0932x over previous
#include <cuda_runtime.h>
#include <cuda_fp16.h>
#include <cstdint>

// MoE grouped GEMM, sm_103 base ISA: plain fp16 mma.sync.m16n8k16, fp32 accum.
// Round 12: CTA 128x128, 8 warps (4x2 grid of 32x64 warp tiles), 2 CTAs/SM
// (__launch_bounds__(256,2)) so barrier/convert phases of one CTA overlap the
// other CTA's MMA work. Direct LDG -> cvt -> STS for A and B (no staging).

#define BM 128
#define BN 128
#define BK 32
#define NTH 256

#define ASTR 40      // halves per A row (80 B) -> conflict-free ldmatrix
#define BSTR 136     // halves per B row (272 B) -> conflict-free ldmatrix.trans

// dynamic smem layout (bytes)
#define AH_OFF(s)  ((s) * 10240)              // 128*80 per stage
#define BH_OFF(s)  (20480 + (s) * 8704)       // 32*272 per stage
#define SMEM_TOTAL 37888

static __device__ __forceinline__ uint32_t smem_u32(const void* p) {
    uint32_t a;
    asm("{ .reg .u64 t; cvta.to.shared.u64 t, %1; cvt.u32.u64 %0, t; }" : "=r"(a) : "l"(p));
    return a;
}
static __device__ __forceinline__ void ldsm4(uint32_t& r0, uint32_t& r1, uint32_t& r2, uint32_t& r3, uint32_t a) {
    asm volatile("ldmatrix.sync.aligned.m8n8.x4.shared.b16 {%0,%1,%2,%3}, [%4];"
                 : "=r"(r0), "=r"(r1), "=r"(r2), "=r"(r3) : "r"(a));
}
static __device__ __forceinline__ void ldsm4t(uint32_t& r0, uint32_t& r1, uint32_t& r2, uint32_t& r3, uint32_t a) {
    asm volatile("ldmatrix.sync.aligned.m8n8.x4.trans.shared.b16 {%0,%1,%2,%3}, [%4];"
                 : "=r"(r0), "=r"(r1), "=r"(r2), "=r"(r3) : "r"(a));
}
static __device__ __forceinline__ void mma16816(float* c, const uint32_t* a, uint32_t b0, uint32_t b1) {
    asm volatile("mma.sync.aligned.m16n8k16.row.col.f32.f16.f16.f32 "
                 "{%0,%1,%2,%3}, {%4,%5,%6,%7}, {%8,%9}, {%0,%1,%2,%3};"
                 : "+f"(c[0]), "+f"(c[1]), "+f"(c[2]), "+f"(c[3])
                 : "r"(a[0]), "r"(a[1]), "r"(a[2]), "r"(a[3]), "r"(b0), "r"(b1));
}
static __device__ __forceinline__ uint32_t h2u(__half2 h) { return *reinterpret_cast<uint32_t*>(&h); }
static __device__ __forceinline__ uint2 cvt4h(float x0, float x1, float x2, float x3) {
    return make_uint2(h2u(__floats2half2_rn(x0, x1)), h2u(__floats2half2_rn(x2, x3)));
}

__global__ __launch_bounds__(NTH, 2)
void moe_mma7(const float* __restrict__ A,
              const int*   __restrict__ gs,
              const float* __restrict__ W,
              const float* __restrict__ bias,
              float*       __restrict__ out,
              int T, int I, int O, int E)
{
    extern __shared__ char smem[];
    const int tid  = threadIdx.x;
    const int wid  = tid >> 5;
    const int lane = tid & 31;
    const int row0 = blockIdx.y * BM;
    const int col0 = blockIdx.x * BN;

    int e = 0, pref = 0;
    while (e < E - 1) {
        int g = __ldg(&gs[e]);
        if (row0 < pref + g) break;
        pref += g; e++;
    }
    const float* __restrict__ Wp = W + (size_t)e * I * O;

    const uint32_t sb = smem_u32(smem);
    // 8 warps: 4 m-rows (wm, 32 each) x 2 n-cols (wn, 64 each)
    const int wm = wid & 3, wn = wid >> 2;

    float acc[2][8][4];
    #pragma unroll
    for (int mi = 0; mi < 2; ++mi)
        #pragma unroll
        for (int ni = 0; ni < 8; ++ni)
            #pragma unroll
            for (int q = 0; q < 4; ++q) acc[mi][ni][q] = 0.f;

    const int nk = I / BK;

    // A: 128 rows x 8 float4 = 1024 -> 4 per thread (rows ar+32*it)
    const int ar = tid >> 3, ac4 = tid & 7;
    // B: 32 rows x 32 float4 = 1024 -> 4 per thread (rows br+8*it), coalesced in O
    const int br = tid >> 5, bc4 = tid & 31;

    float4 pa[4], pb[4];

    // ---- prologue: tile 0 ----
    #pragma unroll
    for (int it = 0; it < 4; ++it)
        pa[it] = *(const float4*)(A + (size_t)(row0 + ar + it * 32) * I + ac4 * 4);
    #pragma unroll
    for (int it = 0; it < 4; ++it)
        pb[it] = *(const float4*)(Wp + (size_t)(br + it * 8) * O + col0 + bc4 * 4);
    #pragma unroll
    for (int it = 0; it < 4; ++it) {
        int r = ar + it * 32;
        *(uint2*)(smem + AH_OFF(0) + r * (ASTR * 2) + ac4 * 8) =
            cvt4h(pa[it].x, pa[it].y, pa[it].z, pa[it].w);
    }
    #pragma unroll
    for (int it = 0; it < 4; ++it) {
        int r = br + it * 8;
        *(uint2*)(smem + BH_OFF(0) + r * (BSTR * 2) + bc4 * 8) =
            cvt4h(pb[it].x, pb[it].y, pb[it].z, pb[it].w);
    }
    __syncthreads();

    for (int kt = 0; kt < nk; ++kt) {
        const int s = kt & 1;
        const bool more = (kt + 1 < nk);

        // issue gmem loads for tile kt+1 (in flight during compute)
        if (more) {
            const int k0 = (kt + 1) * BK;
            #pragma unroll
            for (int it = 0; it < 4; ++it)
                pa[it] = *(const float4*)(A + (size_t)(row0 + ar + it * 32) * I + k0 + ac4 * 4);
            #pragma unroll
            for (int it = 0; it < 4; ++it)
                pb[it] = *(const float4*)(Wp + (size_t)(k0 + br + it * 8) * O + col0 + bc4 * 4);
        }

        // ---- compute stage s: warp tile 32x64, 2 ks of k=16 ----
        const uint32_t sAh = sb + AH_OFF(s), sBh = sb + BH_OFF(s);
        #pragma unroll
        for (int ks = 0; ks < 2; ++ks) {
            uint32_t ah[2][4], bf[4][4];
            #pragma unroll
            for (int mi = 0; mi < 2; ++mi) {
                int row = wm * 32 + mi * 16 + (lane & 15);
                uint32_t off = row * (ASTR * 2) + ks * 32 + (lane >> 4) * 16;
                ldsm4(ah[mi][0], ah[mi][1], ah[mi][2], ah[mi][3], sAh + off);
            }
            #pragma unroll
            for (int nt = 0; nt < 4; ++nt) {
                int krow = ks * 16 + (lane & 15);
                int ncol = wn * 64 + nt * 16 + (lane >> 4) * 8;
                ldsm4t(bf[nt][0], bf[nt][1], bf[nt][2], bf[nt][3],
                       sBh + krow * (BSTR * 2) + ncol * 2);
            }
            #pragma unroll
            for (int mi = 0; mi < 2; ++mi)
                #pragma unroll
                for (int ni = 0; ni < 8; ++ni) {
                    uint32_t b0 = bf[ni >> 1][(ni & 1) * 2];
                    uint32_t b1 = bf[ni >> 1][(ni & 1) * 2 + 1];
                    mma16816(acc[mi][ni], ah[mi], b0, b1);
                }
        }

        // ---- convert tile kt+1 into stage s^1 ----
        if (more) {
            const int d = s ^ 1;
            #pragma unroll
            for (int it = 0; it < 4; ++it) {
                int r = ar + it * 32;
                *(uint2*)(smem + AH_OFF(d) + r * (ASTR * 2) + ac4 * 8) =
                    cvt4h(pa[it].x, pa[it].y, pa[it].z, pa[it].w);
            }
            #pragma unroll
            for (int it = 0; it < 4; ++it) {
                int r = br + it * 8;
                *(uint2*)(smem + BH_OFF(d) + r * (BSTR * 2) + bc4 * 8) =
                    cvt4h(pb[it].x, pb[it].y, pb[it].z, pb[it].w);
            }
        }
        __syncthreads();
    }

    // ---- epilogue: bias + store ----
    #pragma unroll
    for (int mi = 0; mi < 2; ++mi) {
        int r_lo = row0 + wm * 32 + mi * 16 + (lane >> 2);
        #pragma unroll
        for (int ni = 0; ni < 8; ++ni) {
            int col = col0 + wn * 64 + ni * 8 + (lane & 3) * 2;
            float2 bv = *(const float2*)(bias + (size_t)e * O + col);
            float2 v0, v1;
            v0.x = acc[mi][ni][0] + bv.x; v0.y = acc[mi][ni][1] + bv.y;
            v1.x = acc[mi][ni][2] + bv.x; v1.y = acc[mi][ni][3] + bv.y;
            *(float2*)(out + (size_t)r_lo * O + col) = v0;
            *(float2*)(out + (size_t)(r_lo + 8) * O + col) = v1;
        }
    }
}

extern "C" void kernel_launch(void* const* d_in, const int* in_sizes, int n_in,
                              void* d_out, int out_size)
{
    const float* A    = (const float*)d_in[0];
    const int*   gs   = (const int*)  d_in[1];
    const float* W    = (const float*)d_in[2];
    const float* bias = (const float*)d_in[3];
    float*       out  = (float*)d_out;

    const int E = in_sizes[1];
    const int O = in_sizes[3] / E;
    const long long wsz = (long long)in_sizes[2];
    const int I = (int)(wsz / ((long long)E * O));
    const int T = in_sizes[0] / I;

    cudaFuncSetAttribute(moe_mma7, cudaFuncAttributeMaxDynamicSharedMemorySize, SMEM_TOTAL);
    dim3 grid(O / BN, T / BM);
    moe_mma7<<<grid, NTH, SMEM_TOTAL>>>(A, gs, W, bias, out, T, I, O, E);
}

// round 13
// speedup vs baseline: 1.3039x; 1.1927x over previous
#include <cuda_runtime.h>
#include <cuda_fp16.h>
#include <cstdint>

// MoE grouped GEMM, sm_103 base ISA. Round 13:
//  Pass 1: convert A (T x I) and W (E x I x O) fp32 -> fp16 into __device__
//          scratch (one-time streaming pass, bit-identical rounding to r12).
//  Pass 2: pure fp16 HGEMM mainloop: cp.async gmem->smem (4-stage ring),
//          ldmatrix + mma.sync.m16n8k16, fp32 accum, fused bias epilogue.
//  CTA 128x128, 8 warps (4x2 of 32x64 warp tiles), 2 CTAs/SM.

#define BM 128
#define BN 128
#define BK 32
#define NTH 256
#define STAGES 4

#define ASTR 40      // halves per A smem row (80 B) -> conflict-free ldmatrix
#define BSTR 136     // halves per B smem row (272 B) -> conflict-free ldmatrix.trans

#define STG_BYTES 18944                    // A 128*80 + B 32*272
#define A_OFF(s)  ((s) * STG_BYTES)
#define B_OFF(s)  ((s) * STG_BYTES + 10240)
#define SMEM_TOTAL (STAGES * STG_BYTES)    // 75776

// fp16 scratch (problem dims: T=8192, I=2048, E=8, O=4096)
__device__ __half gA16[8192 * 2048];
__device__ __half gB16[(size_t)8 * 2048 * 4096];

static __device__ __forceinline__ uint32_t smem_u32(const void* p) {
    uint32_t a;
    asm("{ .reg .u64 t; cvta.to.shared.u64 t, %1; cvt.u32.u64 %0, t; }" : "=r"(a) : "l"(p));
    return a;
}
static __device__ __forceinline__ void cp_async16(uint32_t s, const void* g) {
    asm volatile("cp.async.cg.shared.global [%0], [%1], 16;" :: "r"(s), "l"(g));
}
#define CP_COMMIT() asm volatile("cp.async.commit_group;" ::: "memory")
#define CP_WAIT(n)  asm volatile("cp.async.wait_group %0;" :: "n"(n) : "memory")

static __device__ __forceinline__ void ldsm4(uint32_t& r0, uint32_t& r1, uint32_t& r2, uint32_t& r3, uint32_t a) {
    asm volatile("ldmatrix.sync.aligned.m8n8.x4.shared.b16 {%0,%1,%2,%3}, [%4];"
                 : "=r"(r0), "=r"(r1), "=r"(r2), "=r"(r3) : "r"(a));
}
static __device__ __forceinline__ void ldsm4t(uint32_t& r0, uint32_t& r1, uint32_t& r2, uint32_t& r3, uint32_t a) {
    asm volatile("ldmatrix.sync.aligned.m8n8.x4.trans.shared.b16 {%0,%1,%2,%3}, [%4];"
                 : "=r"(r0), "=r"(r1), "=r"(r2), "=r"(r3) : "r"(a));
}
static __device__ __forceinline__ void mma16816(float* c, const uint32_t* a, uint32_t b0, uint32_t b1) {
    asm volatile("mma.sync.aligned.m16n8k16.row.col.f32.f16.f16.f32 "
                 "{%0,%1,%2,%3}, {%4,%5,%6,%7}, {%8,%9}, {%0,%1,%2,%3};"
                 : "+f"(c[0]), "+f"(c[1]), "+f"(c[2]), "+f"(c[3])
                 : "r"(a[0]), "r"(a[1]), "r"(a[2]), "r"(a[3]), "r"(b0), "r"(b1));
}
static __device__ __forceinline__ uint32_t h2u(__half2 h) { return *reinterpret_cast<uint32_t*>(&h); }
static __device__ __forceinline__ uint2 cvt4h(float x0, float x1, float x2, float x3) {
    return make_uint2(h2u(__floats2half2_rn(x0, x1)), h2u(__floats2half2_rn(x2, x3)));
}

// ---- pass 1: fp32 -> fp16 streaming converts ----
__global__ void cvtA_kernel(const float4* __restrict__ in, int n4) {
    uint2* out = reinterpret_cast<uint2*>(gA16);
    int i = blockIdx.x * blockDim.x + threadIdx.x;
    int stride = gridDim.x * blockDim.x;
    for (; i < n4; i += stride) {
        float4 v = in[i];
        out[i] = cvt4h(v.x, v.y, v.z, v.w);
    }
}
__global__ void cvtB_kernel(const float4* __restrict__ in, int n4) {
    uint2* out = reinterpret_cast<uint2*>(gB16);
    int i = blockIdx.x * blockDim.x + threadIdx.x;
    int stride = gridDim.x * blockDim.x;
    for (; i < n4; i += stride) {
        float4 v = in[i];
        out[i] = cvt4h(v.x, v.y, v.z, v.w);
    }
}

// issue one pipeline stage: A tile (128x32) + B tile (32x128), fp16, cp.async
static __device__ __forceinline__ void issue_stage(
    uint32_t sb, int s, const __half* Ag, const __half* Bg,
    int k0, int I, int O, int tid)
{
    #pragma unroll
    for (int it = 0; it < 2; ++it) {
        int id = tid + it * NTH;
        int r = id >> 2, c = id & 3;                 // 128 rows x 4 chunks
        cp_async16(sb + A_OFF(s) + r * 80 + c * 16,
                   Ag + (size_t)r * I + k0 + c * 8);
    }
    #pragma unroll
    for (int it = 0; it < 2; ++it) {
        int id = tid + it * NTH;
        int r = id >> 4, c = id & 15;                // 32 rows x 16 chunks
        cp_async16(sb + B_OFF(s) + r * 272 + c * 16,
                   Bg + (size_t)(k0 + r) * O + c * 8);
    }
    CP_COMMIT();
}

__global__ __launch_bounds__(NTH, 2)
void moe_hgemm(const int* __restrict__ gs,
               const float* __restrict__ bias,
               float* __restrict__ out,
               int T, int I, int O, int E)
{
    extern __shared__ char smem[];
    const int tid  = threadIdx.x;
    const int wid  = tid >> 5;
    const int lane = tid & 31;
    const int row0 = blockIdx.y * BM;
    const int col0 = blockIdx.x * BN;

    int e = 0, pref = 0;
    while (e < E - 1) {
        int g = __ldg(&gs[e]);
        if (row0 < pref + g) break;
        pref += g; e++;
    }
    const __half* Ag = gA16 + (size_t)row0 * I;
    const __half* Bg = gB16 + (size_t)e * I * O + col0;

    const uint32_t sb = smem_u32(smem);
    const int wm = wid & 3, wn = wid >> 2;   // 4x2 warp grid, tile 32x64

    float acc[2][8][4];
    #pragma unroll
    for (int mi = 0; mi < 2; ++mi)
        #pragma unroll
        for (int ni = 0; ni < 8; ++ni)
            #pragma unroll
            for (int q = 0; q < 4; ++q) acc[mi][ni][q] = 0.f;

    const int nk = I / BK;

    // prologue: fill STAGES-1 stages
    #pragma unroll
    for (int p = 0; p < STAGES - 1; ++p)
        issue_stage(sb, p, Ag, Bg, p * BK, I, O, tid);

    for (int kt = 0; kt < nk; ++kt) {
        CP_WAIT(STAGES - 2);     // stage kt complete (own groups)
        __syncthreads();         // -> complete for all threads

        const int s = kt & (STAGES - 1);
        const uint32_t sAh = sb + A_OFF(s), sBh = sb + B_OFF(s);
        #pragma unroll
        for (int ks = 0; ks < 2; ++ks) {
            uint32_t ah[2][4], bf[4][4];
            #pragma unroll
            for (int mi = 0; mi < 2; ++mi) {
                int row = wm * 32 + mi * 16 + (lane & 15);
                uint32_t off = row * (ASTR * 2) + ks * 32 + (lane >> 4) * 16;
                ldsm4(ah[mi][0], ah[mi][1], ah[mi][2], ah[mi][3], sAh + off);
            }
            #pragma unroll
            for (int nt = 0; nt < 4; ++nt) {
                int krow = ks * 16 + (lane & 15);
                int ncol = wn * 64 + nt * 16 + (lane >> 4) * 8;
                ldsm4t(bf[nt][0], bf[nt][1], bf[nt][2], bf[nt][3],
                       sBh + krow * (BSTR * 2) + ncol * 2);
            }
            #pragma unroll
            for (int mi = 0; mi < 2; ++mi)
                #pragma unroll
                for (int ni = 0; ni < 8; ++ni) {
                    uint32_t b0 = bf[ni >> 1][(ni & 1) * 2];
                    uint32_t b1 = bf[ni >> 1][(ni & 1) * 2 + 1];
                    mma16816(acc[mi][ni], ah[mi], b0, b1);
                }
        }

        // refill the stage just freed (kt-1's buffer) with tile kt+STAGES-1
        if (kt + STAGES - 1 < nk)
            issue_stage(sb, (kt + STAGES - 1) & (STAGES - 1), Ag, Bg,
                        (kt + STAGES - 1) * BK, I, O, tid);
    }

    // ---- epilogue: bias + store ----
    #pragma unroll
    for (int mi = 0; mi < 2; ++mi) {
        int r_lo = row0 + wm * 32 + mi * 16 + (lane >> 2);
        #pragma unroll
        for (int ni = 0; ni < 8; ++ni) {
            int col = col0 + wn * 64 + ni * 8 + (lane & 3) * 2;
            float2 bv = *(const float2*)(bias + (size_t)e * O + col);
            float2 v0, v1;
            v0.x = acc[mi][ni][0] + bv.x; v0.y = acc[mi][ni][1] + bv.y;
            v1.x = acc[mi][ni][2] + bv.x; v1.y = acc[mi][ni][3] + bv.y;
            *(float2*)(out + (size_t)r_lo * O + col) = v0;
            *(float2*)(out + (size_t)(r_lo + 8) * O + col) = v1;
        }
    }
}

extern "C" void kernel_launch(void* const* d_in, const int* in_sizes, int n_in,
                              void* d_out, int out_size)
{
    const float* A    = (const float*)d_in[0];
    const int*   gs   = (const int*)  d_in[1];
    const float* W    = (const float*)d_in[2];
    const float* bias = (const float*)d_in[3];
    float*       out  = (float*)d_out;

    const int E = in_sizes[1];
    const int O = in_sizes[3] / E;
    const long long wsz = (long long)in_sizes[2];
    const int I = (int)(wsz / ((long long)E * O));
    const int T = in_sizes[0] / I;

    // pass 1: fp32 -> fp16
    cvtA_kernel<<<2048, 256>>>((const float4*)A, (T * I) / 4);
    cvtB_kernel<<<4096, 256>>>((const float4*)W, (int)(wsz / 4));

    // pass 2: fp16 grouped HGEMM
    cudaFuncSetAttribute(moe_hgemm, cudaFuncAttributeMaxDynamicSharedMemorySize, SMEM_TOTAL);
    dim3 grid(O / BN, T / BM);
    moe_hgemm<<<grid, NTH, SMEM_TOTAL>>>(gs, bias, out, T, I, O, E);
}